// round 1
// baseline (speedup 1.0000x reference)
#include <cuda_runtime.h>
#include <math.h>

#define N_NODES 50000
#define N_EDGES 500000
#define HID 256
#define LAYERS 15

// -------- scratch (static device globals; no allocations allowed) --------
__device__ float  g_h  [(size_t)N_NODES * HID];   // node features
__device__ float  g_agg[(size_t)N_NODES * HID];   // neighbor aggregate
__device__ float  g_out[(size_t)N_NODES * HID];   // pre-BN layer output
__device__ float  g_z1 [(size_t)N_EDGES * HID];   // edge MLP hidden
__device__ double g_stats[2 * HID];               // per-channel sum / sumsq
__device__ float  g_bnsc[HID];                    // folded BN scale
__device__ float  g_bnsh[HID];                    // folded BN shift

// ---------------- input fc: h = x @ W_in^T ; zero agg & stats ----------------
__global__ void k_input_fc(const float* __restrict__ x, const float* __restrict__ Win) {
    int idx = blockIdx.x * blockDim.x + threadIdx.x;
    if (idx < 2 * HID) g_stats[idx] = 0.0;
    if (idx >= N_NODES * HID) return;
    int node = idx >> 8;
    int c = idx & 255;
    g_h[idx] = x[node * 2] * Win[c * 2] + x[node * 2 + 1] * Win[c * 2 + 1];
    g_agg[idx] = 0.f;
}

// ---------------- scatter: agg[dst] += h[src] (float4 vector atomics) --------
__global__ void k_scatter(const int* __restrict__ ei) {
    int idx = blockIdx.x * blockDim.x + threadIdx.x;   // N_EDGES*64 = 32M < 2^31
    if (idx >= N_EDGES * 64) return;
    int e = idx >> 6;
    int q = idx & 63;
    int s = __ldg(ei + e);
    int d = __ldg(ei + N_EDGES + e);
    const float4* h4 = (const float4*)g_h;
    float4* a4 = (float4*)g_agg;
    float4 v = h4[(size_t)s * 64 + q];
    atomicAdd(a4 + (size_t)d * 64 + q, v);   // sm_90+ vector atomic
}

// ------- node GEMM: out = agg@Wr^T + h@Wo^T + br  (M=50000,N=256,K=512) ------
__global__ void __launch_bounds__(256, 2)
k_gemm_node(const float* __restrict__ Wr, const float* __restrict__ Wo,
            const float* __restrict__ br) {
    __shared__ float As[8][132];
    __shared__ float Bs[8][132];
    int bm = blockIdx.x * 128;
    int bn = blockIdx.y * 128;
    int tid = threadIdx.x;
    int tx = tid & 15, ty = tid >> 4;
    int lrow = tid >> 1, lseg = (tid & 1) * 4;
    float acc[8][8] = {};

    for (int k0 = 0; k0 < 512; k0 += 8) {
        const float* A = (k0 < 256) ? g_agg : g_h;
        const float* B = (k0 < 256) ? Wr : Wo;
        int kk = k0 & 255;
        float4 av = make_float4(0.f, 0.f, 0.f, 0.f);
        int gr = bm + lrow;
        if (gr < N_NODES) av = *(const float4*)(A + (size_t)gr * HID + kk + lseg);
        As[lseg + 0][lrow] = av.x; As[lseg + 1][lrow] = av.y;
        As[lseg + 2][lrow] = av.z; As[lseg + 3][lrow] = av.w;
        float4 bv = *(const float4*)(B + (size_t)(bn + lrow) * HID + kk + lseg);
        Bs[lseg + 0][lrow] = bv.x; Bs[lseg + 1][lrow] = bv.y;
        Bs[lseg + 2][lrow] = bv.z; Bs[lseg + 3][lrow] = bv.w;
        __syncthreads();
#pragma unroll
        for (int dk = 0; dk < 8; dk++) {
            float a[8], b[8];
            *(float4*)(a)     = *(const float4*)(&As[dk][ty * 8]);
            *(float4*)(a + 4) = *(const float4*)(&As[dk][ty * 8 + 4]);
            *(float4*)(b)     = *(const float4*)(&Bs[dk][tx * 8]);
            *(float4*)(b + 4) = *(const float4*)(&Bs[dk][tx * 8 + 4]);
#pragma unroll
            for (int i = 0; i < 8; i++)
#pragma unroll
                for (int j = 0; j < 8; j++)
                    acc[i][j] = fmaf(a[i], b[j], acc[i][j]);
        }
        __syncthreads();
    }
#pragma unroll
    for (int i = 0; i < 8; i++) {
        int gr = bm + ty * 8 + i;
        if (gr < N_NODES) {
#pragma unroll
            for (int j = 0; j < 8; j += 4) {
                int gc = bn + tx * 8 + j;
                float4 v;
                v.x = acc[i][j + 0] + br[gc + 0];
                v.y = acc[i][j + 1] + br[gc + 1];
                v.z = acc[i][j + 2] + br[gc + 2];
                v.w = acc[i][j + 3] + br[gc + 3];
                *(float4*)(&g_out[(size_t)gr * HID + gc]) = v;
            }
        }
    }
}

// ---------------- BN column stats over 50000 rows (double accum) -------------
__global__ void k_stats() {
    int c = threadIdx.x;
    int r0 = blockIdx.x * 200;
    double s = 0.0, s2 = 0.0;
    for (int r = r0; r < r0 + 200; r++) {
        float v = g_out[(size_t)r * HID + c];
        s += v;
        s2 += (double)v * v;
    }
    atomicAdd(&g_stats[c], s);
    atomicAdd(&g_stats[HID + c], s2);
}

// fold BN into scale/shift; zero stats for next layer
__global__ void k_bn_finalize(const float* __restrict__ gm, const float* __restrict__ bt) {
    int c = threadIdx.x;
    double mean = g_stats[c] * (1.0 / N_NODES);
    double var  = g_stats[HID + c] * (1.0 / N_NODES) - mean * mean;
    float rstd = rsqrtf((float)var + 1e-5f);
    float sc = rstd * gm[c];
    g_bnsc[c] = sc;
    g_bnsh[c] = bt[c] - (float)mean * sc;
    g_stats[c] = 0.0;
    g_stats[HID + c] = 0.0;
}

// h += relu(out*sc + sh); zero agg for next layer's scatter
__global__ void k_bn_apply() {
    int idx = blockIdx.x * blockDim.x + threadIdx.x;  // float4 units: 3.2M
    if (idx >= N_NODES * 64) return;
    int c0 = (idx & 63) * 4;
    float4 o  = ((const float4*)g_out)[idx];
    float4 sc = *(const float4*)(g_bnsc + c0);
    float4 sh = *(const float4*)(g_bnsh + c0);
    float4 hv = ((float4*)g_h)[idx];
    hv.x += fmaxf(fmaf(o.x, sc.x, sh.x), 0.f);
    hv.y += fmaxf(fmaf(o.y, sc.y, sh.y), 0.f);
    hv.z += fmaxf(fmaf(o.z, sc.z, sh.z), 0.f);
    hv.w += fmaxf(fmaf(o.w, sc.w, sh.w), 0.f);
    ((float4*)g_h)[idx] = hv;
    ((float4*)g_agg)[idx] = make_float4(0.f, 0.f, 0.f, 0.f);
}

// ------- edge GEMM1: z1 = relu(cat(h[src],h[dst]) @ W1^T + b1) ---------------
__global__ void __launch_bounds__(256, 2)
k_gemm_edge1(const int* __restrict__ ei, const float* __restrict__ W1,
             const float* __restrict__ b1) {
    __shared__ float As[8][132];
    __shared__ float Bs[8][132];
    int bm = blockIdx.x * 128;
    int bn = blockIdx.y * 128;
    int tid = threadIdx.x;
    int tx = tid & 15, ty = tid >> 4;
    int lrow = tid >> 1, lseg = (tid & 1) * 4;
    float acc[8][8] = {};

    for (int k0 = 0; k0 < 512; k0 += 8) {
        float4 av = make_float4(0.f, 0.f, 0.f, 0.f);
        int gr = bm + lrow;
        if (gr < N_EDGES) {
            int node = __ldg(ei + ((k0 < 256) ? 0 : N_EDGES) + gr);
            av = *(const float4*)(g_h + (size_t)node * HID + (k0 & 255) + lseg);
        }
        As[lseg + 0][lrow] = av.x; As[lseg + 1][lrow] = av.y;
        As[lseg + 2][lrow] = av.z; As[lseg + 3][lrow] = av.w;
        float4 bv = *(const float4*)(W1 + (size_t)(bn + lrow) * 512 + k0 + lseg);
        Bs[lseg + 0][lrow] = bv.x; Bs[lseg + 1][lrow] = bv.y;
        Bs[lseg + 2][lrow] = bv.z; Bs[lseg + 3][lrow] = bv.w;
        __syncthreads();
#pragma unroll
        for (int dk = 0; dk < 8; dk++) {
            float a[8], b[8];
            *(float4*)(a)     = *(const float4*)(&As[dk][ty * 8]);
            *(float4*)(a + 4) = *(const float4*)(&As[dk][ty * 8 + 4]);
            *(float4*)(b)     = *(const float4*)(&Bs[dk][tx * 8]);
            *(float4*)(b + 4) = *(const float4*)(&Bs[dk][tx * 8 + 4]);
#pragma unroll
            for (int i = 0; i < 8; i++)
#pragma unroll
                for (int j = 0; j < 8; j++)
                    acc[i][j] = fmaf(a[i], b[j], acc[i][j]);
        }
        __syncthreads();
    }
#pragma unroll
    for (int i = 0; i < 8; i++) {
        int gr = bm + ty * 8 + i;
        if (gr < N_EDGES) {
#pragma unroll
            for (int j = 0; j < 8; j += 4) {
                int gc = bn + tx * 8 + j;
                float4 v;
                v.x = fmaxf(acc[i][j + 0] + b1[gc + 0], 0.f);
                v.y = fmaxf(acc[i][j + 1] + b1[gc + 1], 0.f);
                v.z = fmaxf(acc[i][j + 2] + b1[gc + 2], 0.f);
                v.w = fmaxf(acc[i][j + 3] + b1[gc + 3], 0.f);
                *(float4*)(&g_z1[(size_t)gr * HID + gc]) = v;
            }
        }
    }
}

// --- edge GEMM2 fused with GEMV3+sigmoid: out=sigmoid(relu(z1@W2^T+b2)@w3+b3)
__global__ void __launch_bounds__(256, 2)
k_gemm_edge2(const float* __restrict__ W2, const float* __restrict__ b2,
             const float* __restrict__ W3, const float* __restrict__ b3,
             float* __restrict__ dout) {
    __shared__ float As[8][68];    // 64 rows (edges)
    __shared__ float Bs[8][260];   // full 256 cols
    int bm = blockIdx.x * 64;
    int tid = threadIdx.x;
    int tx = tid & 31, ty = tid >> 5;   // lanes within one warp share ty
    float acc[8][8] = {};

    for (int k0 = 0; k0 < 256; k0 += 8) {
        if (tid < 128) {
            int lrow = tid >> 1, lseg = (tid & 1) * 4;
            float4 av = make_float4(0.f, 0.f, 0.f, 0.f);
            int gr = bm + lrow;
            if (gr < N_EDGES) av = *(const float4*)(g_z1 + (size_t)gr * HID + k0 + lseg);
            As[lseg + 0][lrow] = av.x; As[lseg + 1][lrow] = av.y;
            As[lseg + 2][lrow] = av.z; As[lseg + 3][lrow] = av.w;
        }
        {
            int n = tid >> 1, lseg = (tid & 1) * 4;
            float4 bv = *(const float4*)(W2 + (size_t)n * HID + k0 + lseg);
            Bs[lseg + 0][n] = bv.x; Bs[lseg + 1][n] = bv.y;
            Bs[lseg + 2][n] = bv.z; Bs[lseg + 3][n] = bv.w;
            float4 bv2 = *(const float4*)(W2 + (size_t)(n + 128) * HID + k0 + lseg);
            Bs[lseg + 0][n + 128] = bv2.x; Bs[lseg + 1][n + 128] = bv2.y;
            Bs[lseg + 2][n + 128] = bv2.z; Bs[lseg + 3][n + 128] = bv2.w;
        }
        __syncthreads();
#pragma unroll
        for (int dk = 0; dk < 8; dk++) {
            float a[8], b[8];
            *(float4*)(a)     = *(const float4*)(&As[dk][ty * 8]);
            *(float4*)(a + 4) = *(const float4*)(&As[dk][ty * 8 + 4]);
            *(float4*)(b)     = *(const float4*)(&Bs[dk][tx * 8]);
            *(float4*)(b + 4) = *(const float4*)(&Bs[dk][tx * 8 + 4]);
#pragma unroll
            for (int i = 0; i < 8; i++)
#pragma unroll
                for (int j = 0; j < 8; j++)
                    acc[i][j] = fmaf(a[i], b[j], acc[i][j]);
        }
        __syncthreads();
    }
    // epilogue: relu + dot with w3 + warp reduce + sigmoid
    float b2l[8], w3l[8];
#pragma unroll
    for (int j = 0; j < 8; j++) {
        b2l[j] = b2[tx * 8 + j];
        w3l[j] = W3[tx * 8 + j];
    }
    float bias3 = b3[0];
#pragma unroll
    for (int i = 0; i < 8; i++) {
        float s = 0.f;
#pragma unroll
        for (int j = 0; j < 8; j++) {
            float z = acc[i][j] + b2l[j];
            z = z > 0.f ? z : 0.f;
            s = fmaf(z, w3l[j], s);
        }
#pragma unroll
        for (int off = 16; off; off >>= 1) s += __shfl_xor_sync(0xffffffffu, s, off);
        if (tx == 0) {
            int gr = bm + ty * 8 + i;
            if (gr < N_EDGES) dout[gr] = 1.f / (1.f + expf(-(s + bias3)));
        }
    }
}

extern "C" void kernel_launch(void* const* d_in, const int* in_sizes, int n_in,
                              void* d_out, int out_size) {
    const float* x     = (const float*)d_in[0];
    const int*   ei    = (const int*)  d_in[1];
    const float* Win   = (const float*)d_in[2];
    const float* Wrel  = (const float*)d_in[3];
    const float* brel  = (const float*)d_in[4];
    const float* Wroot = (const float*)d_in[5];
    const float* gamma = (const float*)d_in[6];
    const float* beta  = (const float*)d_in[7];
    const float* W1    = (const float*)d_in[8];
    const float* b1    = (const float*)d_in[9];
    const float* W2    = (const float*)d_in[10];
    const float* b2    = (const float*)d_in[11];
    const float* W3    = (const float*)d_in[12];
    const float* b3    = (const float*)d_in[13];
    float* out = (float*)d_out;

    k_input_fc<<<(N_NODES * HID + 255) / 256, 256>>>(x, Win);

    for (int l = 0; l < LAYERS; l++) {
        k_scatter<<<(N_EDGES * 64 + 255) / 256, 256>>>(ei);
        dim3 gn((N_NODES + 127) / 128, 2);
        k_gemm_node<<<gn, 256>>>(Wrel + (size_t)l * HID * HID,
                                 Wroot + (size_t)l * HID * HID,
                                 brel + (size_t)l * HID);
        k_stats<<<250, 256>>>();
        k_bn_finalize<<<1, 256>>>(gamma + (size_t)l * HID, beta + (size_t)l * HID);
        k_bn_apply<<<(N_NODES * 64 + 255) / 256, 256>>>();
    }

    dim3 ge1((N_EDGES + 127) / 128, 2);
    k_gemm_edge1<<<ge1, 256>>>(ei, W1, b1);
    k_gemm_edge2<<<(N_EDGES + 63) / 64, 256>>>(W2, b2, W3, b3, out);
}

// round 3
// speedup vs baseline: 1.7206x; 1.7206x over previous
#include <cuda_runtime.h>
#include <cstdint>
#include <math.h>

#define N_NODES 50000
#define N_EDGES 500000
#define HID 256
#define LAYERS 15

// ---------------------------------------------------------------- scratch
__device__ float  g_h  [(size_t)N_NODES * HID];
__device__ float  g_agg[(size_t)N_NODES * HID];
__device__ float  g_out[(size_t)N_NODES * HID];
__device__ float  g_z1 [(size_t)N_EDGES * HID];
__device__ double g_stats[2 * HID];
__device__ float  g_bnsc[HID];
__device__ float  g_bnsh[HID];

// ---------------------------------------------------------------- helpers
__device__ __forceinline__ float to_tf32(float x) {
    uint32_t u;
    asm("cvt.rna.tf32.f32 %0, %1;" : "=r"(u) : "f"(x));
    return __uint_as_float(u);
}

// D += A(16x8 row) * B(8x8 col), tf32 inputs, fp32 accum
__device__ __forceinline__ void mma8(float* c, const float* a, const float* b) {
    asm volatile(
        "mma.sync.aligned.m16n8k8.row.col.f32.tf32.tf32.f32 "
        "{%0,%1,%2,%3}, {%4,%5,%6,%7}, {%8,%9}, {%0,%1,%2,%3};"
        : "+f"(c[0]), "+f"(c[1]), "+f"(c[2]), "+f"(c[3])
        : "r"(__float_as_uint(a[0])), "r"(__float_as_uint(a[1])),
          "r"(__float_as_uint(a[2])), "r"(__float_as_uint(a[3])),
          "r"(__float_as_uint(b[0])), "r"(__float_as_uint(b[1])));
}

// smem strides (floats): %32 == 8 -> conflict-free fragment loads
#define ASTR 136   // A: [16][128] padded
#define BSTR 264   // B: [16][256] padded

// ---------------------------------------------------------------- small kernels
__global__ void k_input_fc(const float* __restrict__ x, const float* __restrict__ Win) {
    int idx = blockIdx.x * blockDim.x + threadIdx.x;
    if (idx < 2 * HID) g_stats[idx] = 0.0;
    if (idx >= N_NODES * HID) return;
    int node = idx >> 8, c = idx & 255;
    g_h[idx] = x[node * 2] * Win[c * 2] + x[node * 2 + 1] * Win[c * 2 + 1];
    g_agg[idx] = 0.f;
}

__global__ void k_scatter(const int* __restrict__ ei) {
    int idx = blockIdx.x * blockDim.x + threadIdx.x;
    if (idx >= N_EDGES * 64) return;
    int e = idx >> 6, q = idx & 63;
    int s = __ldg(ei + e);
    int d = __ldg(ei + N_EDGES + e);
    float4 v = ((const float4*)g_h)[(size_t)s * 64 + q];
    atomicAdd(((float4*)g_agg) + (size_t)d * 64 + q, v);
}

__global__ void k_stats() {
    int c = threadIdx.x;
    int r0 = blockIdx.x * 50;
    double s = 0.0, s2 = 0.0;
    for (int r = r0; r < r0 + 50; r++) {
        float v = g_out[(size_t)r * HID + c];
        s += v; s2 += (double)v * v;
    }
    atomicAdd(&g_stats[c], s);
    atomicAdd(&g_stats[HID + c], s2);
}

__global__ void k_bn_finalize(const float* __restrict__ gm, const float* __restrict__ bt) {
    int c = threadIdx.x;
    double mean = g_stats[c] * (1.0 / N_NODES);
    double var  = g_stats[HID + c] * (1.0 / N_NODES) - mean * mean;
    float rstd = rsqrtf((float)var + 1e-5f);
    float sc = rstd * gm[c];
    g_bnsc[c] = sc;
    g_bnsh[c] = bt[c] - (float)mean * sc;
    g_stats[c] = 0.0; g_stats[HID + c] = 0.0;
}

__global__ void k_bn_apply() {
    int idx = blockIdx.x * blockDim.x + threadIdx.x;
    if (idx >= N_NODES * 64) return;
    int c0 = (idx & 63) * 4;
    float4 o  = ((const float4*)g_out)[idx];
    float4 sc = *(const float4*)(g_bnsc + c0);
    float4 sh = *(const float4*)(g_bnsh + c0);
    float4 hv = ((float4*)g_h)[idx];
    hv.x += fmaxf(fmaf(o.x, sc.x, sh.x), 0.f);
    hv.y += fmaxf(fmaf(o.y, sc.y, sh.y), 0.f);
    hv.z += fmaxf(fmaf(o.z, sc.z, sh.z), 0.f);
    hv.w += fmaxf(fmaf(o.w, sc.w, sh.w), 0.f);
    ((float4*)g_h)[idx] = hv;
    ((float4*)g_agg)[idx] = make_float4(0.f, 0.f, 0.f, 0.f);
}

// =================================================================
// tf32 mma.sync GEMM: 512 thr, 16 warps (4m x 4n), BM=128 BN=256 BK=16
// warp tile 32x64: 2 m-frags x 8 n-frags of m16n8k8
// =================================================================

// compute one BK=16 slab from smem into c[2][8][4]
__device__ __forceinline__ void mma_slab(const float* As, const float* Bs,
                                         int wm, int wn, int lq, int lr,
                                         float c[2][8][4]) {
#pragma unroll
    for (int ks = 0; ks < 16; ks += 8) {
        float bf[8][2];
#pragma unroll
        for (int nt = 0; nt < 8; nt++) {
            int col = wn * 64 + nt * 8 + lq;
            bf[nt][0] = Bs[(ks + lr) * BSTR + col];
            bf[nt][1] = Bs[(ks + 4 + lr) * BSTR + col];
        }
#pragma unroll
        for (int mt = 0; mt < 2; mt++) {
            int row = wm * 32 + mt * 16 + lq;
            float a[4];
            a[0] = As[(ks + lr) * ASTR + row];
            a[1] = As[(ks + lr) * ASTR + row + 8];
            a[2] = As[(ks + 4 + lr) * ASTR + row];
            a[3] = As[(ks + 4 + lr) * ASTR + row + 8];
#pragma unroll
            for (int nt = 0; nt < 8; nt++)
                mma8(c[mt][nt], a, bf[nt]);
        }
    }
}

// ---- node GEMM: out = agg@Wr^T + h@Wo^T + br ----
__global__ void __launch_bounds__(512, 1)
k_gemm_node(const float* __restrict__ Wr, const float* __restrict__ Wo,
            const float* __restrict__ br) {
    __shared__ float As[16 * ASTR];
    __shared__ float Bs[16 * BSTR];
    int tid = threadIdx.x;
    int bm = blockIdx.x * 128;
    int lane = tid & 31, lq = lane >> 2, lr = lane & 3;
    int wid = tid >> 5, wm = wid & 3, wn = wid >> 2;
    float c[2][8][4] = {};

    int am = tid >> 2, aks = (tid & 3) * 4;      // A loader coords
    for (int kt = 0; kt < 32; kt++) {
        int half = kt >> 4;
        int kc = (kt & 15) * 16;
        {   // A: 128x16
            const float* Asrc = half ? g_h : g_agg;
            int gr = bm + am;
            float4 v = make_float4(0.f, 0.f, 0.f, 0.f);
            if (gr < N_NODES) v = __ldg((const float4*)(Asrc + (size_t)gr * HID + kc + aks));
            As[(aks + 0) * ASTR + am] = to_tf32(v.x);
            As[(aks + 1) * ASTR + am] = to_tf32(v.y);
            As[(aks + 2) * ASTR + am] = to_tf32(v.z);
            As[(aks + 3) * ASTR + am] = to_tf32(v.w);
        }
        {   // B: 256x16
            const float* Bsrc = half ? Wo : Wr;
#pragma unroll
            for (int i = 0; i < 2; i++) {
                int idx = tid + i * 512;
                int n = idx >> 2, ks = (idx & 3) * 4;
                float4 v = __ldg((const float4*)(Bsrc + (size_t)n * HID + kc + ks));
                Bs[(ks + 0) * BSTR + n] = to_tf32(v.x);
                Bs[(ks + 1) * BSTR + n] = to_tf32(v.y);
                Bs[(ks + 2) * BSTR + n] = to_tf32(v.z);
                Bs[(ks + 3) * BSTR + n] = to_tf32(v.w);
            }
        }
        __syncthreads();
        mma_slab(As, Bs, wm, wn, lq, lr, c);
        __syncthreads();
    }
    // epilogue: + br, store g_out
#pragma unroll
    for (int mt = 0; mt < 2; mt++) {
        int row = bm + wm * 32 + mt * 16 + lq;
#pragma unroll
        for (int nt = 0; nt < 8; nt++) {
            int col = wn * 64 + nt * 8 + lr * 2;
            float2 bb = __ldg((const float2*)(br + col));
            if (row < N_NODES) {
                float2 o = make_float2(c[mt][nt][0] + bb.x, c[mt][nt][1] + bb.y);
                *(float2*)(g_out + (size_t)row * HID + col) = o;
            }
            if (row + 8 < N_NODES) {
                float2 o = make_float2(c[mt][nt][2] + bb.x, c[mt][nt][3] + bb.y);
                *(float2*)(g_out + (size_t)(row + 8) * HID + col) = o;
            }
        }
    }
}

// ---- edge GEMM1: z1 = relu(cat(h[src],h[dst]) @ W1^T + b1) ----
__global__ void __launch_bounds__(512, 1)
k_gemm_edge1(const int* __restrict__ ei, const float* __restrict__ W1,
             const float* __restrict__ b1) {
    __shared__ float As[16 * ASTR];
    __shared__ float Bs[16 * BSTR];
    int tid = threadIdx.x;
    int bm = blockIdx.x * 128;
    int lane = tid & 31, lq = lane >> 2, lr = lane & 3;
    int wid = tid >> 5, wm = wid & 3, wn = wid >> 2;
    float c[2][8][4] = {};

    int am = tid >> 2, aks = (tid & 3) * 4;
    int e = bm + am;
    bool val = e < N_EDGES;
    int nsrc = val ? __ldg(ei + e) : 0;
    int ndst = val ? __ldg(ei + N_EDGES + e) : 0;

    for (int kt = 0; kt < 32; kt++) {
        int half = kt >> 4;
        int kc = (kt & 15) * 16;
        {   // A: gathered rows of h
            int node = half ? ndst : nsrc;
            float4 v = make_float4(0.f, 0.f, 0.f, 0.f);
            if (val) v = __ldg((const float4*)(g_h + (size_t)node * HID + kc + aks));
            As[(aks + 0) * ASTR + am] = to_tf32(v.x);
            As[(aks + 1) * ASTR + am] = to_tf32(v.y);
            As[(aks + 2) * ASTR + am] = to_tf32(v.z);
            As[(aks + 3) * ASTR + am] = to_tf32(v.w);
        }
        {   // B: W1 rows (K=512 contiguous)
#pragma unroll
            for (int i = 0; i < 2; i++) {
                int idx = tid + i * 512;
                int n = idx >> 2, ks = (idx & 3) * 4;
                float4 v = __ldg((const float4*)(W1 + (size_t)n * 512 + kt * 16 + ks));
                Bs[(ks + 0) * BSTR + n] = to_tf32(v.x);
                Bs[(ks + 1) * BSTR + n] = to_tf32(v.y);
                Bs[(ks + 2) * BSTR + n] = to_tf32(v.z);
                Bs[(ks + 3) * BSTR + n] = to_tf32(v.w);
            }
        }
        __syncthreads();
        mma_slab(As, Bs, wm, wn, lq, lr, c);
        __syncthreads();
    }
#pragma unroll
    for (int mt = 0; mt < 2; mt++) {
        int row = bm + wm * 32 + mt * 16 + lq;
#pragma unroll
        for (int nt = 0; nt < 8; nt++) {
            int col = wn * 64 + nt * 8 + lr * 2;
            float2 bb = __ldg((const float2*)(b1 + col));
            if (row < N_EDGES) {
                float2 o = make_float2(fmaxf(c[mt][nt][0] + bb.x, 0.f),
                                       fmaxf(c[mt][nt][1] + bb.y, 0.f));
                *(float2*)(g_z1 + (size_t)row * HID + col) = o;
            }
            if (row + 8 < N_EDGES) {
                float2 o = make_float2(fmaxf(c[mt][nt][2] + bb.x, 0.f),
                                       fmaxf(c[mt][nt][3] + bb.y, 0.f));
                *(float2*)(g_z1 + (size_t)(row + 8) * HID + col) = o;
            }
        }
    }
}

// ---- edge GEMM2 + GEMV3 + sigmoid ----
__global__ void __launch_bounds__(512, 1)
k_gemm_edge2(const float* __restrict__ W2, const float* __restrict__ b2,
             const float* __restrict__ W3, const float* __restrict__ b3,
             float* __restrict__ dout) {
    __shared__ float As[16 * ASTR];
    __shared__ float Bs[16 * BSTR];
    __shared__ float sred[4][128];
    int tid = threadIdx.x;
    int bm = blockIdx.x * 128;
    int lane = tid & 31, lq = lane >> 2, lr = lane & 3;
    int wid = tid >> 5, wm = wid & 3, wn = wid >> 2;
    float c[2][8][4] = {};

    int am = tid >> 2, aks = (tid & 3) * 4;
    int e = bm + am;
    bool val = e < N_EDGES;

    for (int kt = 0; kt < 16; kt++) {
        int kc = kt * 16;
        {
            float4 v = make_float4(0.f, 0.f, 0.f, 0.f);
            if (val) v = __ldg((const float4*)(g_z1 + (size_t)e * HID + kc + aks));
            As[(aks + 0) * ASTR + am] = to_tf32(v.x);
            As[(aks + 1) * ASTR + am] = to_tf32(v.y);
            As[(aks + 2) * ASTR + am] = to_tf32(v.z);
            As[(aks + 3) * ASTR + am] = to_tf32(v.w);
        }
        {
#pragma unroll
            for (int i = 0; i < 2; i++) {
                int idx = tid + i * 512;
                int n = idx >> 2, ks = (idx & 3) * 4;
                float4 v = __ldg((const float4*)(W2 + (size_t)n * HID + kc + ks));
                Bs[(ks + 0) * BSTR + n] = to_tf32(v.x);
                Bs[(ks + 1) * BSTR + n] = to_tf32(v.y);
                Bs[(ks + 2) * BSTR + n] = to_tf32(v.z);
                Bs[(ks + 3) * BSTR + n] = to_tf32(v.w);
            }
        }
        __syncthreads();
        mma_slab(As, Bs, wm, wn, lq, lr, c);
        __syncthreads();
    }

    // partial dot per thread over its fragment cols
#pragma unroll
    for (int mt = 0; mt < 2; mt++) {
        float p0 = 0.f, p1 = 0.f;
#pragma unroll
        for (int nt = 0; nt < 8; nt++) {
            int col = wn * 64 + nt * 8 + lr * 2;
            float2 bb = __ldg((const float2*)(b2 + col));
            float2 ww = __ldg((const float2*)(W3 + col));
            p0 = fmaf(fmaxf(c[mt][nt][0] + bb.x, 0.f), ww.x, p0);
            p0 = fmaf(fmaxf(c[mt][nt][1] + bb.y, 0.f), ww.y, p0);
            p1 = fmaf(fmaxf(c[mt][nt][2] + bb.x, 0.f), ww.x, p1);
            p1 = fmaf(fmaxf(c[mt][nt][3] + bb.y, 0.f), ww.y, p1);
        }
        // reduce across lane%4 (bits 0-1)
        p0 += __shfl_xor_sync(0xffffffffu, p0, 1);
        p0 += __shfl_xor_sync(0xffffffffu, p0, 2);
        p1 += __shfl_xor_sync(0xffffffffu, p1, 1);
        p1 += __shfl_xor_sync(0xffffffffu, p1, 2);
        if (lr == 0) {
            sred[wn][wm * 32 + mt * 16 + lq] = p0;
            sred[wn][wm * 32 + mt * 16 + lq + 8] = p1;
        }
    }
    __syncthreads();
    if (tid < 128) {
        int gr = bm + tid;
        if (gr < N_EDGES) {
            float s = sred[0][tid] + sred[1][tid] + sred[2][tid] + sred[3][tid] + __ldg(b3);
            dout[gr] = 1.f / (1.f + expf(-s));
        }
    }
}

// ---------------------------------------------------------------- launch
extern "C" void kernel_launch(void* const* d_in, const int* in_sizes, int n_in,
                              void* d_out, int out_size) {
    const float* x     = (const float*)d_in[0];
    const int*   ei    = (const int*)  d_in[1];
    const float* Win   = (const float*)d_in[2];
    const float* Wrel  = (const float*)d_in[3];
    const float* brel  = (const float*)d_in[4];
    const float* Wroot = (const float*)d_in[5];
    const float* gamma = (const float*)d_in[6];
    const float* beta  = (const float*)d_in[7];
    const float* W1    = (const float*)d_in[8];
    const float* b1    = (const float*)d_in[9];
    const float* W2    = (const float*)d_in[10];
    const float* b2    = (const float*)d_in[11];
    const float* W3    = (const float*)d_in[12];
    const float* b3    = (const float*)d_in[13];
    float* out = (float*)d_out;

    k_input_fc<<<(N_NODES * HID + 255) / 256, 256>>>(x, Win);

    int node_grid = (N_NODES + 127) / 128;   // 391
    for (int l = 0; l < LAYERS; l++) {
        k_scatter<<<(N_EDGES * 64 + 255) / 256, 256>>>(ei);
        k_gemm_node<<<node_grid, 512>>>(Wrel + (size_t)l * HID * HID,
                                        Wroot + (size_t)l * HID * HID,
                                        brel + (size_t)l * HID);
        k_stats<<<1000, 256>>>();
        k_bn_finalize<<<1, 256>>>(gamma + (size_t)l * HID, beta + (size_t)l * HID);
        k_bn_apply<<<(N_NODES * 64 + 255) / 256, 256>>>();
    }

    int edge_grid = (N_EDGES + 127) / 128;   // 3907
    k_gemm_edge1<<<edge_grid, 512>>>(ei, W1, b1);
    k_gemm_edge2<<<edge_grid, 512>>>(W2, b2, W3, b3, out);
}

// round 4
// speedup vs baseline: 2.3682x; 1.3763x over previous
#include <cuda_runtime.h>
#include <cstdint>
#include <math.h>

#define N_NODES 50000
#define N_EDGES 500000
#define HID 256
#define LAYERS 15

// ---------------------------------------------------------------- scratch
__device__ float g_h  [(size_t)N_NODES * HID];
__device__ float g_agg[(size_t)N_NODES * HID];
__device__ float g_out[(size_t)N_NODES * HID];
__device__ float g_z1 [(size_t)N_EDGES * HID];
__device__ float g_statsf[2 * HID];
__device__ float g_bnsc[HID];
__device__ float g_bnsh[HID];
// CSR
__device__ int g_deg[N_NODES];
__device__ int g_off[N_NODES + 1];
__device__ int g_pos[N_NODES];
__device__ int g_srcs[N_EDGES];

// ---------------------------------------------------------------- helpers
__device__ __forceinline__ float to_tf32(float x) {
    uint32_t u;
    asm("cvt.rna.tf32.f32 %0, %1;" : "=r"(u) : "f"(x));
    return __uint_as_float(u);
}
__device__ __forceinline__ void mma8(float* c, const float* a, const float* b) {
    asm volatile(
        "mma.sync.aligned.m16n8k8.row.col.f32.tf32.tf32.f32 "
        "{%0,%1,%2,%3}, {%4,%5,%6,%7}, {%8,%9}, {%0,%1,%2,%3};"
        : "+f"(c[0]), "+f"(c[1]), "+f"(c[2]), "+f"(c[3])
        : "r"(__float_as_uint(a[0])), "r"(__float_as_uint(a[1])),
          "r"(__float_as_uint(a[2])), "r"(__float_as_uint(a[3])),
          "r"(__float_as_uint(b[0])), "r"(__float_as_uint(b[1])));
}

#define ASTR 136
#define BSTR 264
#define STAGE (16 * ASTR + 16 * BSTR)        // 6400 floats
#define SMEM_BYTES (2 * STAGE * 4)           // 51200 B

// ---------------------------------------------------------------- small kernels
__global__ void k_input_fc(const float* __restrict__ x, const float* __restrict__ Win) {
    int idx = blockIdx.x * blockDim.x + threadIdx.x;
    if (idx < 2 * HID) g_statsf[idx] = 0.f;
    if (idx < N_NODES) g_deg[idx] = 0;
    if (idx >= N_NODES * HID) return;
    int node = idx >> 8, c = idx & 255;
    g_h[idx] = x[node * 2] * Win[c * 2] + x[node * 2 + 1] * Win[c * 2 + 1];
}

// ---- CSR build (once per launch) ----
__global__ void k_csr_count(const int* __restrict__ ei) {
    int e = blockIdx.x * blockDim.x + threadIdx.x;
    if (e >= N_EDGES) return;
    atomicAdd(&g_deg[__ldg(ei + N_EDGES + e)], 1);
}

__global__ void k_csr_scan() {     // 1 block, 1024 threads
    __shared__ int wsum[32];
    __shared__ int s_carry;
    int tid = threadIdx.x, lane = tid & 31, wid = tid >> 5;
    if (tid == 0) s_carry = 0;
    __syncthreads();
    for (int base = 0; base < N_NODES; base += 1024) {
        int i = base + tid;
        int v = (i < N_NODES) ? g_deg[i] : 0;
        int x = v;
#pragma unroll
        for (int d = 1; d < 32; d <<= 1) {
            int y = __shfl_up_sync(0xffffffffu, x, d);
            if (lane >= d) x += y;
        }
        if (lane == 31) wsum[wid] = x;
        __syncthreads();
        if (wid == 0) {
            int w = wsum[lane];
#pragma unroll
            for (int d = 1; d < 32; d <<= 1) {
                int y = __shfl_up_sync(0xffffffffu, w, d);
                if (lane >= d) w += y;
            }
            wsum[lane] = w;
        }
        __syncthreads();
        int carry = s_carry;
        int incl = x + (wid > 0 ? wsum[wid - 1] : 0);
        if (i < N_NODES) {
            int excl = carry + incl - v;
            g_off[i] = excl;
            g_pos[i] = excl;
        }
        __syncthreads();
        if (tid == 0) s_carry = carry + wsum[31];
        __syncthreads();
    }
    if (threadIdx.x == 0) g_off[N_NODES] = s_carry;
}

__global__ void k_csr_fill(const int* __restrict__ ei) {
    int e = blockIdx.x * blockDim.x + threadIdx.x;
    if (e >= N_EDGES) return;
    int d = __ldg(ei + N_EDGES + e);
    int p = atomicAdd(&g_pos[d], 1);
    g_srcs[p] = __ldg(ei + e);
}

// ---- gather: agg[n] = sum_{e: dst=n} h[src[e]] ; warp per node ----
__global__ void k_gather() {
    int gw = (blockIdx.x * blockDim.x + threadIdx.x) >> 5;
    int lane = threadIdx.x & 31;
    if (gw >= N_NODES) return;
    int beg = g_off[gw], end = g_off[gw + 1];
    float4 a0 = make_float4(0.f, 0.f, 0.f, 0.f);
    float4 a1 = make_float4(0.f, 0.f, 0.f, 0.f);
    for (int i = beg; i < end; i++) {
        int s = __ldg(&g_srcs[i]);
        const float4* hp = (const float4*)(g_h + (size_t)s * HID);
        float4 v0 = __ldg(hp + lane);
        float4 v1 = __ldg(hp + lane + 32);
        a0.x += v0.x; a0.y += v0.y; a0.z += v0.z; a0.w += v0.w;
        a1.x += v1.x; a1.y += v1.y; a1.z += v1.z; a1.w += v1.w;
    }
    float4* ap = (float4*)(g_agg + (size_t)gw * HID);
    ap[lane] = a0;
    ap[lane + 32] = a1;
}

__global__ void k_bn_finalize(const float* __restrict__ gm, const float* __restrict__ bt) {
    int c = threadIdx.x;
    float mean = g_statsf[c] * (1.f / N_NODES);
    float var  = g_statsf[HID + c] * (1.f / N_NODES) - mean * mean;
    float rstd = rsqrtf(var + 1e-5f);
    float sc = rstd * gm[c];
    g_bnsc[c] = sc;
    g_bnsh[c] = bt[c] - mean * sc;
    g_statsf[c] = 0.f; g_statsf[HID + c] = 0.f;
}

__global__ void k_bn_apply() {
    int idx = blockIdx.x * blockDim.x + threadIdx.x;
    if (idx >= N_NODES * 64) return;
    int c0 = (idx & 63) * 4;
    float4 o  = ((const float4*)g_out)[idx];
    float4 sc = *(const float4*)(g_bnsc + c0);
    float4 sh = *(const float4*)(g_bnsh + c0);
    float4 hv = ((float4*)g_h)[idx];
    hv.x += fmaxf(fmaf(o.x, sc.x, sh.x), 0.f);
    hv.y += fmaxf(fmaf(o.y, sc.y, sh.y), 0.f);
    hv.z += fmaxf(fmaf(o.z, sc.z, sh.z), 0.f);
    hv.w += fmaxf(fmaf(o.w, sc.w, sh.w), 0.f);
    ((float4*)g_h)[idx] = hv;
}

// =================================================================
// pipelined tf32 mma.sync GEMM: 512 thr, 16 warps (4m x 4n),
// BM=128 BN=256 BK=16, warp tile 32x64, double-buffered smem
// =================================================================
__device__ __forceinline__ void mma_slab(const float* As, const float* Bs,
                                         int wm, int wn, int lq, int lr,
                                         float c[2][8][4]) {
#pragma unroll
    for (int ks = 0; ks < 16; ks += 8) {
        float bf[8][2];
#pragma unroll
        for (int nt = 0; nt < 8; nt++) {
            int col = wn * 64 + nt * 8 + lq;
            bf[nt][0] = Bs[(ks + lr) * BSTR + col];
            bf[nt][1] = Bs[(ks + 4 + lr) * BSTR + col];
        }
#pragma unroll
        for (int mt = 0; mt < 2; mt++) {
            int row = wm * 32 + mt * 16 + lq;
            float a[4];
            a[0] = As[(ks + lr) * ASTR + row];
            a[1] = As[(ks + lr) * ASTR + row + 8];
            a[2] = As[(ks + 4 + lr) * ASTR + row];
            a[3] = As[(ks + 4 + lr) * ASTR + row + 8];
#pragma unroll
            for (int nt = 0; nt < 8; nt++)
                mma8(c[mt][nt], a, bf[nt]);
        }
    }
}

__device__ __forceinline__ void store_slab(float* As, float* Bs, int am, int aks,
                                           float4 ra, float4 rb0, float4 rb1) {
    As[(aks + 0) * ASTR + am] = to_tf32(ra.x);
    As[(aks + 1) * ASTR + am] = to_tf32(ra.y);
    As[(aks + 2) * ASTR + am] = to_tf32(ra.z);
    As[(aks + 3) * ASTR + am] = to_tf32(ra.w);
    Bs[(aks + 0) * BSTR + am] = to_tf32(rb0.x);
    Bs[(aks + 1) * BSTR + am] = to_tf32(rb0.y);
    Bs[(aks + 2) * BSTR + am] = to_tf32(rb0.z);
    Bs[(aks + 3) * BSTR + am] = to_tf32(rb0.w);
    Bs[(aks + 0) * BSTR + am + 128] = to_tf32(rb1.x);
    Bs[(aks + 1) * BSTR + am + 128] = to_tf32(rb1.y);
    Bs[(aks + 2) * BSTR + am + 128] = to_tf32(rb1.z);
    Bs[(aks + 3) * BSTR + am + 128] = to_tf32(rb1.w);
}

// ---- node GEMM: out = agg@Wr^T + h@Wo^T + br, fused BN stats ----
__global__ void __launch_bounds__(512, 1)
k_gemm_node(const float* __restrict__ Wr, const float* __restrict__ Wo,
            const float* __restrict__ br) {
    extern __shared__ float sm[];
    float* Asb[2] = {sm, sm + STAGE};
    float* Bsb[2] = {sm + 16 * ASTR, sm + STAGE + 16 * ASTR};
    int tid = threadIdx.x;
    int bm = blockIdx.x * 128;
    int lane = tid & 31, lq = lane >> 2, lr = lane & 3;
    int wid = tid >> 5, wm = wid & 3, wn = wid >> 2;
    int am = tid >> 2, aks = (tid & 3) * 4;
    int gr = bm + am;
    bool arow = gr < N_NODES;
    float c[2][8][4] = {};

    float4 ra, rb0, rb1;
    {   // prefetch kt = 0
        ra = arow ? __ldg((const float4*)(g_agg + (size_t)gr * HID + aks))
                  : make_float4(0.f, 0.f, 0.f, 0.f);
        rb0 = __ldg((const float4*)(Wr + (size_t)am * HID + aks));
        rb1 = __ldg((const float4*)(Wr + (size_t)(am + 128) * HID + aks));
    }
    for (int kt = 0; kt < 32; kt++) {
        int b = kt & 1;
        store_slab(Asb[b], Bsb[b], am, aks, ra, rb0, rb1);
        float4 na = ra, nb0 = rb0, nb1 = rb1;
        if (kt < 31) {
            int k2 = kt + 1;
            int half = k2 >> 4, kc = (k2 & 15) * 16;
            const float* Asrc = half ? g_h : g_agg;
            const float* Bsrc = half ? Wo : Wr;
            na = arow ? __ldg((const float4*)(Asrc + (size_t)gr * HID + kc + aks))
                      : make_float4(0.f, 0.f, 0.f, 0.f);
            nb0 = __ldg((const float4*)(Bsrc + (size_t)am * HID + kc + aks));
            nb1 = __ldg((const float4*)(Bsrc + (size_t)(am + 128) * HID + kc + aks));
        }
        __syncthreads();
        mma_slab(Asb[b], Bsb[b], wm, wn, lq, lr, c);
        ra = na; rb0 = nb0; rb1 = nb1;
    }

    // epilogue: +br, store g_out, accumulate BN stats (fp32)
    float ps[8][2], pq[8][2];
#pragma unroll
    for (int nt = 0; nt < 8; nt++)
        ps[nt][0] = ps[nt][1] = pq[nt][0] = pq[nt][1] = 0.f;

#pragma unroll
    for (int mt = 0; mt < 2; mt++) {
        int row = bm + wm * 32 + mt * 16 + lq;
        bool v0 = row < N_NODES, v1 = (row + 8) < N_NODES;
#pragma unroll
        for (int nt = 0; nt < 8; nt++) {
            int col = wn * 64 + nt * 8 + lr * 2;
            float2 bb = __ldg((const float2*)(br + col));
            float o0 = c[mt][nt][0] + bb.x, o1 = c[mt][nt][1] + bb.y;
            float o2 = c[mt][nt][2] + bb.x, o3 = c[mt][nt][3] + bb.y;
            if (v0) {
                *(float2*)(g_out + (size_t)row * HID + col) = make_float2(o0, o1);
                ps[nt][0] += o0; pq[nt][0] += o0 * o0;
                ps[nt][1] += o1; pq[nt][1] += o1 * o1;
            }
            if (v1) {
                *(float2*)(g_out + (size_t)(row + 8) * HID + col) = make_float2(o2, o3);
                ps[nt][0] += o2; pq[nt][0] += o2 * o2;
                ps[nt][1] += o3; pq[nt][1] += o3 * o3;
            }
        }
    }
    // reduce over lq (lane bits 2..4), then lanes 0-3 do atomics
#pragma unroll
    for (int nt = 0; nt < 8; nt++)
#pragma unroll
        for (int u = 0; u < 2; u++) {
#pragma unroll
            for (int d = 4; d < 32; d <<= 1) {
                ps[nt][u] += __shfl_xor_sync(0xffffffffu, ps[nt][u], d);
                pq[nt][u] += __shfl_xor_sync(0xffffffffu, pq[nt][u], d);
            }
        }
    if (lq == 0) {
#pragma unroll
        for (int nt = 0; nt < 8; nt++) {
            int col = wn * 64 + nt * 8 + lr * 2;
            atomicAdd(&g_statsf[col], ps[nt][0]);
            atomicAdd(&g_statsf[col + 1], ps[nt][1]);
            atomicAdd(&g_statsf[HID + col], pq[nt][0]);
            atomicAdd(&g_statsf[HID + col + 1], pq[nt][1]);
        }
    }
}

// ---- edge GEMM1: z1 = relu(cat(h[src],h[dst]) @ W1^T + b1) ----
__global__ void __launch_bounds__(512, 1)
k_gemm_edge1(const int* __restrict__ ei, const float* __restrict__ W1,
             const float* __restrict__ b1) {
    extern __shared__ float sm[];
    float* Asb[2] = {sm, sm + STAGE};
    float* Bsb[2] = {sm + 16 * ASTR, sm + STAGE + 16 * ASTR};
    int tid = threadIdx.x;
    int bm = blockIdx.x * 128;
    int lane = tid & 31, lq = lane >> 2, lr = lane & 3;
    int wid = tid >> 5, wm = wid & 3, wn = wid >> 2;
    int am = tid >> 2, aks = (tid & 3) * 4;
    int e = bm + am;
    bool val = e < N_EDGES;
    int nsrc = val ? __ldg(ei + e) : 0;
    int ndst = val ? __ldg(ei + N_EDGES + e) : 0;
    float c[2][8][4] = {};

    float4 ra, rb0, rb1;
    {
        ra = val ? __ldg((const float4*)(g_h + (size_t)nsrc * HID + aks))
                 : make_float4(0.f, 0.f, 0.f, 0.f);
        rb0 = __ldg((const float4*)(W1 + (size_t)am * 512 + aks));
        rb1 = __ldg((const float4*)(W1 + (size_t)(am + 128) * 512 + aks));
    }
    for (int kt = 0; kt < 32; kt++) {
        int b = kt & 1;
        store_slab(Asb[b], Bsb[b], am, aks, ra, rb0, rb1);
        float4 na = ra, nb0 = rb0, nb1 = rb1;
        if (kt < 31) {
            int k2 = kt + 1;
            int half = k2 >> 4, kc = (k2 & 15) * 16;
            int node = half ? ndst : nsrc;
            na = val ? __ldg((const float4*)(g_h + (size_t)node * HID + kc + aks))
                     : make_float4(0.f, 0.f, 0.f, 0.f);
            nb0 = __ldg((const float4*)(W1 + (size_t)am * 512 + k2 * 16 + aks));
            nb1 = __ldg((const float4*)(W1 + (size_t)(am + 128) * 512 + k2 * 16 + aks));
        }
        __syncthreads();
        mma_slab(Asb[b], Bsb[b], wm, wn, lq, lr, c);
        ra = na; rb0 = nb0; rb1 = nb1;
    }
#pragma unroll
    for (int mt = 0; mt < 2; mt++) {
        int row = bm + wm * 32 + mt * 16 + lq;
#pragma unroll
        for (int nt = 0; nt < 8; nt++) {
            int col = wn * 64 + nt * 8 + lr * 2;
            float2 bb = __ldg((const float2*)(b1 + col));
            if (row < N_EDGES) {
                float2 o = make_float2(fmaxf(c[mt][nt][0] + bb.x, 0.f),
                                       fmaxf(c[mt][nt][1] + bb.y, 0.f));
                *(float2*)(g_z1 + (size_t)row * HID + col) = o;
            }
            if (row + 8 < N_EDGES) {
                float2 o = make_float2(fmaxf(c[mt][nt][2] + bb.x, 0.f),
                                       fmaxf(c[mt][nt][3] + bb.y, 0.f));
                *(float2*)(g_z1 + (size_t)(row + 8) * HID + col) = o;
            }
        }
    }
}

// ---- edge GEMM2 + GEMV3 + sigmoid ----
__global__ void __launch_bounds__(512, 1)
k_gemm_edge2(const float* __restrict__ W2, const float* __restrict__ b2,
             const float* __restrict__ W3, const float* __restrict__ b3,
             float* __restrict__ dout) {
    extern __shared__ float sm[];
    float* Asb[2] = {sm, sm + STAGE};
    float* Bsb[2] = {sm + 16 * ASTR, sm + STAGE + 16 * ASTR};
    __shared__ float sred[4][128];
    int tid = threadIdx.x;
    int bm = blockIdx.x * 128;
    int lane = tid & 31, lq = lane >> 2, lr = lane & 3;
    int wid = tid >> 5, wm = wid & 3, wn = wid >> 2;
    int am = tid >> 2, aks = (tid & 3) * 4;
    int e = bm + am;
    bool val = e < N_EDGES;
    float c[2][8][4] = {};

    float4 ra, rb0, rb1;
    {
        ra = val ? __ldg((const float4*)(g_z1 + (size_t)e * HID + aks))
                 : make_float4(0.f, 0.f, 0.f, 0.f);
        rb0 = __ldg((const float4*)(W2 + (size_t)am * HID + aks));
        rb1 = __ldg((const float4*)(W2 + (size_t)(am + 128) * HID + aks));
    }
    for (int kt = 0; kt < 16; kt++) {
        int b = kt & 1;
        store_slab(Asb[b], Bsb[b], am, aks, ra, rb0, rb1);
        float4 na = ra, nb0 = rb0, nb1 = rb1;
        if (kt < 15) {
            int kc = (kt + 1) * 16;
            na = val ? __ldg((const float4*)(g_z1 + (size_t)e * HID + kc + aks))
                     : make_float4(0.f, 0.f, 0.f, 0.f);
            nb0 = __ldg((const float4*)(W2 + (size_t)am * HID + kc + aks));
            nb1 = __ldg((const float4*)(W2 + (size_t)(am + 128) * HID + kc + aks));
        }
        __syncthreads();
        mma_slab(Asb[b], Bsb[b], wm, wn, lq, lr, c);
        ra = na; rb0 = nb0; rb1 = nb1;
    }

#pragma unroll
    for (int mt = 0; mt < 2; mt++) {
        float p0 = 0.f, p1 = 0.f;
#pragma unroll
        for (int nt = 0; nt < 8; nt++) {
            int col = wn * 64 + nt * 8 + lr * 2;
            float2 bb = __ldg((const float2*)(b2 + col));
            float2 ww = __ldg((const float2*)(W3 + col));
            p0 = fmaf(fmaxf(c[mt][nt][0] + bb.x, 0.f), ww.x, p0);
            p0 = fmaf(fmaxf(c[mt][nt][1] + bb.y, 0.f), ww.y, p0);
            p1 = fmaf(fmaxf(c[mt][nt][2] + bb.x, 0.f), ww.x, p1);
            p1 = fmaf(fmaxf(c[mt][nt][3] + bb.y, 0.f), ww.y, p1);
        }
        p0 += __shfl_xor_sync(0xffffffffu, p0, 1);
        p0 += __shfl_xor_sync(0xffffffffu, p0, 2);
        p1 += __shfl_xor_sync(0xffffffffu, p1, 1);
        p1 += __shfl_xor_sync(0xffffffffu, p1, 2);
        if (lr == 0) {
            sred[wn][wm * 32 + mt * 16 + lq] = p0;
            sred[wn][wm * 32 + mt * 16 + lq + 8] = p1;
        }
    }
    __syncthreads();
    if (tid < 128) {
        int gr = bm + tid;
        if (gr < N_EDGES) {
            float s = sred[0][tid] + sred[1][tid] + sred[2][tid] + sred[3][tid] + __ldg(b3);
            dout[gr] = 1.f / (1.f + expf(-s));
        }
    }
}

// ---------------------------------------------------------------- launch
extern "C" void kernel_launch(void* const* d_in, const int* in_sizes, int n_in,
                              void* d_out, int out_size) {
    const float* x     = (const float*)d_in[0];
    const int*   ei    = (const int*)  d_in[1];
    const float* Win   = (const float*)d_in[2];
    const float* Wrel  = (const float*)d_in[3];
    const float* brel  = (const float*)d_in[4];
    const float* Wroot = (const float*)d_in[5];
    const float* gamma = (const float*)d_in[6];
    const float* beta  = (const float*)d_in[7];
    const float* W1    = (const float*)d_in[8];
    const float* b1    = (const float*)d_in[9];
    const float* W2    = (const float*)d_in[10];
    const float* b2    = (const float*)d_in[11];
    const float* W3    = (const float*)d_in[12];
    const float* b3    = (const float*)d_in[13];
    float* out = (float*)d_out;

    cudaFuncSetAttribute(k_gemm_node,  cudaFuncAttributeMaxDynamicSharedMemorySize, SMEM_BYTES);
    cudaFuncSetAttribute(k_gemm_edge1, cudaFuncAttributeMaxDynamicSharedMemorySize, SMEM_BYTES);
    cudaFuncSetAttribute(k_gemm_edge2, cudaFuncAttributeMaxDynamicSharedMemorySize, SMEM_BYTES);

    k_input_fc<<<(N_NODES * HID + 255) / 256, 256>>>(x, Win);
    k_csr_count<<<(N_EDGES + 255) / 256, 256>>>(ei);
    k_csr_scan<<<1, 1024>>>();
    k_csr_fill<<<(N_EDGES + 255) / 256, 256>>>(ei);

    int node_grid = (N_NODES + 127) / 128;     // 391
    int gather_grid = (N_NODES * 32 + 255) / 256;
    for (int l = 0; l < LAYERS; l++) {
        k_gather<<<gather_grid, 256>>>();
        k_gemm_node<<<node_grid, 512, SMEM_BYTES>>>(
            Wrel + (size_t)l * HID * HID, Wroot + (size_t)l * HID * HID,
            brel + (size_t)l * HID);
        k_bn_finalize<<<1, 256>>>(gamma + (size_t)l * HID, beta + (size_t)l * HID);
        k_bn_apply<<<(N_NODES * 64 + 255) / 256, 256>>>();
    }

    int edge_grid = (N_EDGES + 127) / 128;     // 3907
    k_gemm_edge1<<<edge_grid, 512, SMEM_BYTES>>>(ei, W1, b1);
    k_gemm_edge2<<<edge_grid, 512, SMEM_BYTES>>>(W2, b2, W3, b3, out);
}